// round 1
// baseline (speedup 1.0000x reference)
#include <cuda_runtime.h>
#include <stdint.h>

#define NFULL 512
#define DIMF  64
#define H1    260   // 2*EIN
#define MD    17
#define CHID  68
#define NMAX  460
#define TI    4

// ---------------- device scratch (no allocations allowed) ----------------
__device__ uint32_t g_ugbits[NFULL*16];
__device__ uint32_t g_ug2bits[NFULL*16];
__device__ int      g_idx[NFULL];
__device__ uint32_t g_gsub[NMAX*16];
__device__ float    g_hc[NMAX*DIMF];
__device__ float    g_cA[NMAX*3];
__device__ float    g_cB[NMAX*3];
__device__ float    g_Arow[NMAX*H1];
__device__ float    g_Brow[NMAX*H1];
__device__ float    g_mi[NMAX*MD];

__device__ __forceinline__ float siluf(float x){
    return x / (1.0f + __expf(-x));
}

// ---------------- misc kernels ----------------
__global__ void k_zero_out(float* out){
    int t = blockIdx.x*blockDim.x + threadIdx.x;
    if (t < NFULL*DIMF) out[t] = 0.0f;
}

__global__ void k_ugbits(const float* __restrict__ edge){
    int a = blockIdx.x, c = threadIdx.x;
    bool b = edge[a*NFULL + c] != 0.0f;
    unsigned m = __ballot_sync(0xffffffffu, b);
    if ((c & 31) == 0) g_ugbits[a*16 + (c>>5)] = m;
}

// ug2 = (ug @ ug != 0) via bitset row ORs
__global__ void k_ug2(){
    __shared__ uint32_t row[16];
    int a = blockIdx.x, lane = threadIdx.x;
    if (lane < 16) row[lane] = g_ugbits[a*16 + lane];
    __syncwarp();
    uint32_t acc = 0;
    for (int c = 0; c < NFULL; c++){
        if ((row[c>>5] >> (c&31)) & 1u){
            if (lane < 16) acc |= g_ugbits[c*16 + lane];
        }
    }
    if (lane < 16) g_ug2bits[a*16 + lane] = acc;
}

// scores + top-k selection + gather (set semantics: EGNN is permutation-equivariant)
__global__ void k_select(const float* __restrict__ feat, const float* __restrict__ coor,
                         const float* __restrict__ wp, const float* __restrict__ bp,
                         int pool, int kcnt){
    __shared__ float ss[NFULL];
    __shared__ int   flag[NFULL];
    int a = threadIdx.x;
    const float* w = wp + pool*DIMF;
    float acc = bp[pool];
    for (int d = 0; d < DIMF; d++) acc = fmaf(feat[a*DIMF + d], w[d], acc);
    float s = 1.0f / (1.0f + __expf(-acc));
    ss[a] = s;
    __syncthreads();
    int r = 0;
    for (int b = 0; b < NFULL; b++){
        float sb = ss[b];
        r += (sb > s) || (sb == s && b < a);
    }
    int sel = (r < kcnt) ? 1 : 0;
    flag[a] = sel;
    __syncthreads();
    if (sel){
        int pos = 0;
        for (int b = 0; b < a; b++) pos += flag[b];
        g_idx[pos] = a;
        for (int d = 0; d < DIMF; d++) g_hc[pos*DIMF + d] = feat[a*DIMF + d] * s;
        g_cA[pos*3+0] = coor[a*3+0];
        g_cA[pos*3+1] = coor[a*3+1];
        g_cA[pos*3+2] = coor[a*3+2];
    }
}

// compact adjacency bitrows over the selected index set
__global__ void k_gsub(int n){
    int i = blockIdx.x, lane = threadIdx.x;
    int gi = g_idx[i];
    for (int w = 0; w < 16; w++){
        int j = w*32 + lane;
        bool bit = false;
        if (j < n){
            int gj = g_idx[j];
            bit = (g_ug2bits[gi*16 + (gj>>5)] >> (gj&31)) & 1u;
        }
        unsigned m = __ballot_sync(0xffffffffu, bit);
        if (lane == 0) g_gsub[i*16 + w] = m;
    }
}

// per-node halves of the first edge-MLP layer: A = h@We1[0:64] + be1, B = h@We1[64:128]
__global__ void k_AB(int n, const float* __restrict__ We1L, const float* __restrict__ be1L){
    __shared__ float h[DIMF];
    int i = blockIdx.x, tid = threadIdx.x;
    if (tid < DIMF) h[tid] = g_hc[i*DIMF + tid];
    __syncthreads();
    for (int k = tid; k < H1; k += 256){
        float a = be1L[k], b = 0.0f;
        #pragma unroll
        for (int d = 0; d < DIMF; d++){
            a = fmaf(h[d], We1L[d*H1 + k], a);
            b = fmaf(h[d], We1L[(DIMF + d)*H1 + k], b);
        }
        g_Arow[i*H1 + k] = a;
        g_Brow[i*H1 + k] = b;
    }
}

// zero m_i, init coor_next = coor_cur
__global__ void k_init(int n, int flag){
    float* cnext = flag ? g_cA : g_cB;
    const float* ccur = flag ? g_cB : g_cA;
    int t = blockIdx.x*blockDim.x + threadIdx.x;
    if (t < n*MD) g_mi[t] = 0.0f;
    else {
        int u = t - n*MD;
        if (u < n*3) cnext[u] = ccur[u];
    }
}

// ---------------- the heavy edge kernel ----------------
// block = 128 threads = 4 warps, warp wi handles node row i = blockIdx.x*4 + wi,
// lanes handle 32 j's per chunk; grid.y = 2-way j split.
__global__ void __launch_bounds__(128) k_edge(int n, int flag,
    const float* __restrict__ We1L, const float* __restrict__ We2L,
    const float* __restrict__ be2L, const float* __restrict__ Wc1L,
    const float* __restrict__ bc1L, const float* __restrict__ Wc2L,
    const float* __restrict__ bc2L)
{
    extern __shared__ float sm[];
    float* ws   = sm;               // 260*20 = 5200 (We2 padded, float4-readable)
    float* Bs   = ws + 5200;        // 260*33 = 8580 (B tile transposed, padded)
    float* As   = Bs + 8580;        // 4*260 = 1040
    float* wd   = As + 1040;        // 260
    float* we   = wd + 260;         // 260
    float* wc1  = we + 260;         // 1156 (16B aligned: 15340 floats offset)
    float* bc1s = wc1 + 1156;       // 68
    float* wc2s = bc1s + 68;        // 68
    float* be2s = wc2s + 68;        // 20
    float* cj   = be2s + 20;        // 96
    float* bc2s = cj + 96;          // 1    -> total 16749 floats = 66996 B

    int tid = threadIdx.x, lane = tid & 31, wi = tid >> 5;
    const float* ccur = flag ? g_cB : g_cA;
    float* cnext = flag ? g_cA : g_cB;

    for (int t = tid; t < 5200; t += 128) ws[t] = 0.0f;
    __syncthreads();
    for (int t = tid; t < H1*MD; t += 128){
        int k = t / MD, c = t - k*MD;
        ws[k*20 + c] = We2L[t];
    }
    for (int t = tid; t < H1; t += 128){
        wd[t] = We1L[128*H1 + t];
        we[t] = We1L[129*H1 + t];
    }
    for (int t = tid; t < MD*CHID; t += 128) wc1[t] = Wc1L[t];
    if (tid < CHID){ bc1s[tid] = bc1L[tid]; wc2s[tid] = Wc2L[tid]; }
    if (tid < 20) be2s[tid] = (tid < MD) ? be2L[tid] : 0.0f;
    if (tid == 0) bc2s[0] = bc2L[0];

    int i0 = blockIdx.x * TI;
    for (int e = tid; e < TI*H1; e += 128){
        int w = e / H1, k = e - w*H1;
        int ii = i0 + w;
        As[e] = (ii < n) ? g_Arow[ii*H1 + k] : 0.0f;
    }

    int i = i0 + wi;
    bool iv = (i < n);
    float cix = 0, ciy = 0, ciz = 0;
    const uint32_t* grow = g_gsub + i*16;
    if (iv){ cix = ccur[i*3]; ciy = ccur[i*3+1]; ciz = ccur[i*3+2]; }

    float macc[MD];
    #pragma unroll
    for (int t = 0; t < MD; t++) macc[t] = 0.0f;
    float crx = 0, cry = 0, crz = 0;

    int nch = (n + 31) >> 5;
    for (int ch = blockIdx.y; ch < nch; ch += 2){
        int j0 = ch << 5;
        __syncthreads();
        for (int e = tid; e < 32*H1; e += 128){
            int jj = e / H1, k = e - jj*H1;
            int j = j0 + jj;
            Bs[k*33 + jj] = (j < n) ? g_Brow[j*H1 + k] : 0.0f;
        }
        for (int t = tid; t < 96; t += 128){
            int c = t / 32, jj = t - c*32;
            int j = j0 + jj;
            cj[t] = (j < n) ? ccur[j*3 + c] : 0.0f;
        }
        __syncthreads();
        if (!iv) continue;

        int j = j0 + lane;
        bool jv = (j < n);
        float rx = cix - cj[lane], ry = ciy - cj[32+lane], rz = ciz - cj[64+lane];
        float dist = rx*rx + ry*ry + rz*rz;
        float ge = ((grow[ch] >> lane) & 1u) ? 1.0f : 0.0f;

        float m0[20];
        #pragma unroll
        for (int t = 0; t < 20; t++) m0[t] = be2s[t];
        const float* Aw = As + wi*H1;

        #pragma unroll 2
        for (int k = 0; k < H1; k++){
            float pre = Aw[k] + Bs[k*33 + lane];
            pre = fmaf(dist, wd[k], pre);
            pre = fmaf(ge,   we[k], pre);
            float s = siluf(pre);
            const float4* q = (const float4*)(ws + k*20);
            float4 q0 = q[0], q1 = q[1], q2 = q[2], q3 = q[3], q4 = q[4];
            m0[0]  = fmaf(s, q0.x, m0[0]);  m0[1]  = fmaf(s, q0.y, m0[1]);
            m0[2]  = fmaf(s, q0.z, m0[2]);  m0[3]  = fmaf(s, q0.w, m0[3]);
            m0[4]  = fmaf(s, q1.x, m0[4]);  m0[5]  = fmaf(s, q1.y, m0[5]);
            m0[6]  = fmaf(s, q1.z, m0[6]);  m0[7]  = fmaf(s, q1.w, m0[7]);
            m0[8]  = fmaf(s, q2.x, m0[8]);  m0[9]  = fmaf(s, q2.y, m0[9]);
            m0[10] = fmaf(s, q2.z, m0[10]); m0[11] = fmaf(s, q2.w, m0[11]);
            m0[12] = fmaf(s, q3.x, m0[12]); m0[13] = fmaf(s, q3.y, m0[13]);
            m0[14] = fmaf(s, q3.z, m0[14]); m0[15] = fmaf(s, q3.w, m0[15]);
            m0[16] = fmaf(s, q4.x, m0[16]); m0[17] = fmaf(s, q4.y, m0[17]);
            m0[18] = fmaf(s, q4.z, m0[18]); m0[19] = fmaf(s, q4.w, m0[19]);
        }

        float me[MD];
        #pragma unroll
        for (int t = 0; t < MD; t++) me[t] = siluf(m0[t]);

        // cw = silu(me @ Wc1 + bc1) @ Wc2 + bc2
        float cw = bc2s[0];
        const float4* wc14 = (const float4*)wc1;
        const float4* bc14 = (const float4*)bc1s;
        const float4* wc24 = (const float4*)wc2s;
        #pragma unroll 1
        for (int a4 = 0; a4 < CHID/4; a4++){
            float4 acc = bc14[a4];
            #pragma unroll
            for (int t = 0; t < MD; t++){
                float4 wv = wc14[t*(CHID/4) + a4];
                acc.x = fmaf(me[t], wv.x, acc.x);
                acc.y = fmaf(me[t], wv.y, acc.y);
                acc.z = fmaf(me[t], wv.z, acc.z);
                acc.w = fmaf(me[t], wv.w, acc.w);
            }
            float4 w2 = wc24[a4];
            cw = fmaf(siluf(acc.x), w2.x, cw);
            cw = fmaf(siluf(acc.y), w2.y, cw);
            cw = fmaf(siluf(acc.z), w2.z, cw);
            cw = fmaf(siluf(acc.w), w2.w, cw);
        }

        if (jv){
            #pragma unroll
            for (int t = 0; t < MD; t++) macc[t] += me[t];
            crx = fmaf(cw, rx, crx);
            cry = fmaf(cw, ry, cry);
            crz = fmaf(cw, rz, crz);
        }
    }

    if (iv){
        #pragma unroll
        for (int t = 0; t < MD; t++){
            float v = macc[t];
            for (int off = 16; off; off >>= 1) v += __shfl_xor_sync(0xffffffffu, v, off);
            if (lane == 0) atomicAdd(&g_mi[i*MD + t], v);
        }
        float v;
        v = crx; for (int off = 16; off; off >>= 1) v += __shfl_xor_sync(0xffffffffu, v, off);
        if (lane == 0) atomicAdd(&cnext[i*3 + 0], v);
        v = cry; for (int off = 16; off; off >>= 1) v += __shfl_xor_sync(0xffffffffu, v, off);
        if (lane == 0) atomicAdd(&cnext[i*3 + 1], v);
        v = crz; for (int off = 16; off; off >>= 1) v += __shfl_xor_sync(0xffffffffu, v, off);
        if (lane == 0) atomicAdd(&cnext[i*3 + 2], v);
    }
}

// node MLP + double residual + relu: hc = relu(2*hc + MLP([hc, m_i]))
__global__ void k_node(int n, const float* __restrict__ Wn1L, const float* __restrict__ bn1L,
                       const float* __restrict__ Wn2L, const float* __restrict__ bn2L){
    __shared__ float in[81];
    __shared__ float z[128];
    int i = blockIdx.x, tid = threadIdx.x;
    if (tid < DIMF) in[tid] = g_hc[i*DIMF + tid];
    else if (tid < 81) in[tid] = g_mi[i*MD + (tid - DIMF)];
    __syncthreads();
    float acc = bn1L[tid];
    #pragma unroll 1
    for (int k = 0; k < 81; k++) acc = fmaf(in[k], Wn1L[k*128 + tid], acc);
    z[tid] = siluf(acc);
    __syncthreads();
    if (tid < DIMF){
        float a2 = bn2L[tid];
        #pragma unroll 1
        for (int k = 0; k < 128; k++) a2 = fmaf(z[k], Wn2L[k*DIMF + tid], a2);
        float v = 2.0f*in[tid] + a2;
        g_hc[i*DIMF + tid] = fmaxf(v, 0.0f);
    }
}

__global__ void k_scatter(float* out){
    int i = blockIdx.x, t = threadIdx.x;
    int a = g_idx[i];
    float v = g_hc[i*DIMF + t];
    float* o = &out[a*DIMF + t];
    *o = fmaxf(*o, v);
}

// ---------------- host ----------------
extern "C" void kernel_launch(void* const* d_in, const int* in_sizes, int n_in,
                              void* d_out, int out_size){
    const float* feat = (const float*)d_in[0];
    const float* coor = (const float*)d_in[1];
    const float* edge = (const float*)d_in[2];
    const float* We1  = (const float*)d_in[3];
    const float* be1  = (const float*)d_in[4];
    const float* We2  = (const float*)d_in[5];
    const float* be2  = (const float*)d_in[6];
    const float* Wc1  = (const float*)d_in[7];
    const float* bc1  = (const float*)d_in[8];
    const float* Wc2  = (const float*)d_in[9];
    const float* bc2  = (const float*)d_in[10];
    const float* Wn1  = (const float*)d_in[11];
    const float* bn1  = (const float*)d_in[12];
    const float* Wn2  = (const float*)d_in[13];
    const float* bn2  = (const float*)d_in[14];
    const float* wp   = (const float*)d_in[15];
    const float* bp   = (const float*)d_in[16];
    float* out = (float*)d_out;

    static const int KC[3] = {460, 358, 307}; // max(2, int(k*512)) for 0.9/0.7/0.6
    const int EDGE_SMEM = 16749 * 4;          // 66996 B
    cudaFuncSetAttribute(k_edge, cudaFuncAttributeMaxDynamicSharedMemorySize, 67584);

    k_zero_out<<<128, 256>>>(out);
    k_ugbits<<<512, 512>>>(edge);
    k_ug2<<<512, 32>>>();

    for (int p = 0; p < 3; p++){
        int n = KC[p];
        k_select<<<1, 512>>>(feat, coor, wp, bp, p, n);
        k_gsub<<<n, 32>>>(n);
        for (int l = 0; l < 3; l++){
            k_AB<<<n, 256>>>(n, We1 + l*130*H1, be1 + l*H1);
            int gi = (n*(MD+3) + 255) / 256;
            k_init<<<gi, 256>>>(n, l & 1);
            dim3 ge((n + TI - 1) / TI, 2);
            k_edge<<<ge, 128, EDGE_SMEM>>>(n, l & 1,
                We1 + l*130*H1, We2 + l*H1*MD, be2 + l*MD,
                Wc1 + l*MD*CHID, bc1 + l*CHID, Wc2 + l*CHID, bc2 + l);
            k_node<<<n, 128>>>(n, Wn1 + l*81*128, bn1 + l*128, Wn2 + l*128*DIMF, bn2 + l*DIMF);
        }
        k_scatter<<<n, 64>>>(out);
    }
}

// round 2
// speedup vs baseline: 2.3920x; 2.3920x over previous
#include <cuda_runtime.h>
#include <stdint.h>

#define NFULL 512
#define DIMF  64
#define H1    260   // 2*EIN
#define MD    17
#define CHID  68
#define NMAX  460
#define RPB   8     // rows per block (4 warps x 2 rows)
#define NSPL  5     // j-chunk split factor

// ---------------- device scratch ----------------
__device__ uint32_t g_ugbits[NFULL*16];
__device__ uint32_t g_ug2bits[NFULL*16];
__device__ float    g_scores[NFULL];
__device__ int      g_idx[NFULL];
__device__ uint32_t g_gsub[NMAX*16];
__device__ float    g_hc[NMAX*DIMF];
__device__ float    g_cA[NMAX*3];
__device__ float    g_cB[NMAX*3];
__device__ float    g_Arow[NMAX*H1];
__device__ float    g_Brow[NMAX*H1];
__device__ float    g_mi[NMAX*MD];

__device__ __forceinline__ float siluf(float x){
    return __fdividef(x, 1.0f + __expf(-x));   // MUFU.EX2 + MUFU.RCP, no slow div
}

// ---------------- misc kernels ----------------
__global__ void k_zero_out(float* out){
    int t = blockIdx.x*blockDim.x + threadIdx.x;
    if (t < NFULL*DIMF) out[t] = 0.0f;
}

__global__ void k_ugbits(const float* __restrict__ edge){
    int a = blockIdx.x, c = threadIdx.x;
    bool b = edge[a*NFULL + c] != 0.0f;
    unsigned m = __ballot_sync(0xffffffffu, b);
    if ((c & 31) == 0) g_ugbits[a*16 + (c>>5)] = m;
}

__global__ void k_ug2(){
    __shared__ uint32_t row[16];
    int a = blockIdx.x, lane = threadIdx.x;
    if (lane < 16) row[lane] = g_ugbits[a*16 + lane];
    __syncwarp();
    uint32_t acc = 0;
    for (int c = 0; c < NFULL; c++){
        if ((row[c>>5] >> (c&31)) & 1u){
            if (lane < 16) acc |= g_ugbits[c*16 + lane];
        }
    }
    if (lane < 16) g_ug2bits[a*16 + lane] = acc;
}

// sigmoid scores, one warp per node
__global__ void k_scores(const float* __restrict__ feat, const float* __restrict__ wp,
                         const float* __restrict__ bp, int pool){
    int tid = threadIdx.x, lane = tid & 31;
    int a = blockIdx.x*4 + (tid >> 5);
    const float* w = wp + pool*DIMF;
    float v = feat[a*DIMF + lane]*w[lane] + feat[a*DIMF + 32 + lane]*w[32 + lane];
    for (int off = 16; off; off >>= 1) v += __shfl_xor_sync(0xffffffffu, v, off);
    if (lane == 0){
        v += bp[pool];
        g_scores[a] = __fdividef(1.0f, 1.0f + __expf(-v));
    }
}

// stable top-k by rank counting (set semantics; EGNN is permutation-equivariant)
__global__ void k_select2(int kcnt){
    __shared__ float ss[NFULL];
    __shared__ int   flag[NFULL];
    int a = threadIdx.x;
    float s = g_scores[a];
    ss[a] = s;
    __syncthreads();
    int r = 0;
    for (int b = 0; b < NFULL; b++){
        float sb = ss[b];
        r += (sb > s) || (sb == s && b < a);
    }
    int sel = (r < kcnt) ? 1 : 0;
    flag[a] = sel;
    __syncthreads();
    if (sel){
        int pos = 0;
        for (int b = 0; b < a; b++) pos += flag[b];
        g_idx[pos] = a;
    }
}

__global__ void k_gather(const float* __restrict__ feat, const float* __restrict__ coor){
    int i = blockIdx.x, t = threadIdx.x;
    int a = g_idx[i];
    float s = g_scores[a];
    g_hc[i*DIMF + t] = feat[a*DIMF + t] * s;
    if (t < 3) g_cA[i*3 + t] = coor[a*3 + t];
}

__global__ void k_gsub(int n){
    int i = blockIdx.x, lane = threadIdx.x;
    int gi = g_idx[i];
    for (int w = 0; w < 16; w++){
        int j = w*32 + lane;
        bool bit = false;
        if (j < n){
            int gj = g_idx[j];
            bit = (g_ug2bits[gi*16 + (gj>>5)] >> (gj&31)) & 1u;
        }
        unsigned m = __ballot_sync(0xffffffffu, bit);
        if (lane == 0) g_gsub[i*16 + w] = m;
    }
}

// A = h@We1[0:64] + be1, B = h@We1[64:128]
__global__ void k_AB(int n, const float* __restrict__ We1L, const float* __restrict__ be1L){
    __shared__ float h[DIMF];
    int i = blockIdx.x, tid = threadIdx.x;
    if (tid < DIMF) h[tid] = g_hc[i*DIMF + tid];
    __syncthreads();
    for (int k = tid; k < H1; k += 256){
        float a = be1L[k], b = 0.0f;
        #pragma unroll
        for (int d = 0; d < DIMF; d++){
            a = fmaf(h[d], We1L[d*H1 + k], a);
            b = fmaf(h[d], We1L[(DIMF + d)*H1 + k], b);
        }
        g_Arow[i*H1 + k] = a;
        g_Brow[i*H1 + k] = b;
    }
}

__global__ void k_init(int n, int flag){
    float* cnext = flag ? g_cA : g_cB;
    const float* ccur = flag ? g_cB : g_cA;
    int t = blockIdx.x*blockDim.x + threadIdx.x;
    if (t < n*MD) g_mi[t] = 0.0f;
    else {
        int u = t - n*MD;
        if (u < n*3) cnext[u] = ccur[u];
    }
}

// ---------------- the heavy edge kernel ----------------
// 128 threads = 4 warps; warp wi handles rows (i0+2wi, i0+2wi+1) sharing lane j.
__global__ void __launch_bounds__(128) k_edge(int n, int flag,
    const float* __restrict__ We1L, const float* __restrict__ We2L,
    const float* __restrict__ be2L, const float* __restrict__ Wc1L,
    const float* __restrict__ bc1L, const float* __restrict__ Wc2L,
    const float* __restrict__ bc2L)
{
    extern __shared__ float sm[];
    float* ws   = sm;               // 260*20 = 5200 (We2, float4 rows, 17 used)
    float* Bs   = ws + 5200;        // 260*33 = 8580 (B tile, k-major, padded)
    float* As2  = Bs + 8580;        // 260*8  = 2080 (A tile, k-major, row pairs)
    float* wde  = As2 + 2080;       // 260*2  = 520  (wd,we interleaved)
    float* wc1  = wde + 520;        // 1156
    float* bc1s = wc1 + 1156;       // 68
    float* wc2s = bc1s + 68;        // 68
    float* be2s = wc2s + 68;        // 20 (17 used)
    float* cj   = be2s + 20;        // 96
    float* bc2s = cj + 96;          // 4 pad   -> total 17792 floats = 71168 B

    int tid = threadIdx.x, lane = tid & 31, wi = tid >> 5;
    const float* ccur = flag ? g_cB : g_cA;
    float* cnext = flag ? g_cA : g_cB;

    for (int t = tid; t < H1*MD; t += 128){
        int k = t / MD, c = t - k*MD;
        ws[k*20 + c] = We2L[t];
    }
    for (int t = tid; t < H1; t += 128){
        wde[t*2 + 0] = We1L[128*H1 + t];
        wde[t*2 + 1] = We1L[129*H1 + t];
    }
    for (int t = tid; t < MD*CHID; t += 128) wc1[t] = Wc1L[t];
    if (tid < CHID){ bc1s[tid] = bc1L[tid]; wc2s[tid] = Wc2L[tid]; }
    if (tid < MD) be2s[tid] = be2L[tid];
    if (tid == 0) bc2s[0] = bc2L[0];

    int i0 = blockIdx.x * RPB;
    for (int e = tid; e < RPB*H1; e += 128){
        int r = e / H1, k = e - r*H1;     // coalesced global read along k
        int ii = i0 + r;
        As2[k*8 + r] = (ii < n) ? g_Arow[ii*H1 + k] : 0.0f;
    }

    int ia = i0 + 2*wi, ib = ia + 1;
    bool iv0 = (ia < n), iv1 = (ib < n);
    float c0x=0,c0y=0,c0z=0,c1x=0,c1y=0,c1z=0;
    if (iv0){ c0x=ccur[ia*3]; c0y=ccur[ia*3+1]; c0z=ccur[ia*3+2]; }
    if (iv1){ c1x=ccur[ib*3]; c1y=ccur[ib*3+1]; c1z=ccur[ib*3+2]; }
    const uint32_t* grow0 = g_gsub + ia*16;
    const uint32_t* grow1 = g_gsub + ib*16;

    float macc0[MD], macc1[MD];
    #pragma unroll
    for (int t = 0; t < MD; t++){ macc0[t] = 0.0f; macc1[t] = 0.0f; }
    float cr0x=0,cr0y=0,cr0z=0, cr1x=0,cr1y=0,cr1z=0;

    const float4* wc14 = (const float4*)wc1;
    const float4* bc14 = (const float4*)bc1s;
    const float4* wc24 = (const float4*)wc2s;

    int nch = (n + 31) >> 5;
    for (int ch = blockIdx.y; ch < nch; ch += NSPL){
        int j0 = ch << 5;
        __syncthreads();
        for (int e = tid; e < 32*H1; e += 128){
            int jj = e / H1, k = e - jj*H1;
            int j = j0 + jj;
            Bs[k*33 + jj] = (j < n) ? g_Brow[j*H1 + k] : 0.0f;
        }
        for (int t = tid; t < 96; t += 128){
            int c = t / 32, jj = t - c*32;
            int j = j0 + jj;
            cj[t] = (j < n) ? ccur[j*3 + c] : 0.0f;
        }
        __syncthreads();
        if (!iv0) continue;   // all staging/syncs above run unconditionally

        int j = j0 + lane;
        bool jv = (j < n);
        float jx = cj[lane], jy = cj[32+lane], jz = cj[64+lane];
        float r0x = c0x-jx, r0y = c0y-jy, r0z = c0z-jz;
        float r1x = c1x-jx, r1y = c1y-jy, r1z = c1z-jz;
        float d0 = r0x*r0x + r0y*r0y + r0z*r0z;
        float d1 = r1x*r1x + r1y*r1y + r1z*r1z;
        uint32_t gb0 = grow0[ch];
        uint32_t gb1 = iv1 ? grow1[ch] : 0u;
        float ge0 = ((gb0 >> lane) & 1u) ? 1.0f : 0.0f;
        float ge1 = ((gb1 >> lane) & 1u) ? 1.0f : 0.0f;

        float m0a[MD], m0b[MD];
        #pragma unroll
        for (int t = 0; t < MD; t++){ m0a[t] = be2s[t]; m0b[t] = m0a[t]; }

        #pragma unroll 2
        for (int k = 0; k < H1; k++){
            float2 ap = *(const float2*)(As2 + k*8 + 2*wi);
            float2 wv = *(const float2*)(wde + 2*k);
            float bsv = Bs[k*33 + lane];
            float p0 = ap.x + bsv; p0 = fmaf(d0, wv.x, p0); p0 = fmaf(ge0, wv.y, p0);
            float p1 = ap.y + bsv; p1 = fmaf(d1, wv.x, p1); p1 = fmaf(ge1, wv.y, p1);
            float s0 = siluf(p0), s1 = siluf(p1);
            float qv[MD];
            *(float4*)(qv+0)  = ((const float4*)(ws + k*20))[0];
            *(float4*)(qv+4)  = ((const float4*)(ws + k*20))[1];
            *(float4*)(qv+8)  = ((const float4*)(ws + k*20))[2];
            *(float4*)(qv+12) = ((const float4*)(ws + k*20))[3];
            qv[16] = ws[k*20 + 16];
            #pragma unroll
            for (int t = 0; t < MD; t++){
                m0a[t] = fmaf(s0, qv[t], m0a[t]);
                m0b[t] = fmaf(s1, qv[t], m0b[t]);
            }
        }

        float me0[MD], me1[MD];
        #pragma unroll
        for (int t = 0; t < MD; t++){ me0[t] = siluf(m0a[t]); me1[t] = siluf(m0b[t]); }

        float cw0 = bc2s[0], cw1 = cw0;
        #pragma unroll 1
        for (int a4 = 0; a4 < CHID/4; a4++){
            float4 acc0 = bc14[a4];
            float4 acc1 = acc0;
            #pragma unroll
            for (int t = 0; t < MD; t++){
                float4 wv = wc14[t*(CHID/4) + a4];
                acc0.x = fmaf(me0[t], wv.x, acc0.x);
                acc0.y = fmaf(me0[t], wv.y, acc0.y);
                acc0.z = fmaf(me0[t], wv.z, acc0.z);
                acc0.w = fmaf(me0[t], wv.w, acc0.w);
                acc1.x = fmaf(me1[t], wv.x, acc1.x);
                acc1.y = fmaf(me1[t], wv.y, acc1.y);
                acc1.z = fmaf(me1[t], wv.z, acc1.z);
                acc1.w = fmaf(me1[t], wv.w, acc1.w);
            }
            float4 w2 = wc24[a4];
            cw0 = fmaf(siluf(acc0.x), w2.x, cw0);
            cw0 = fmaf(siluf(acc0.y), w2.y, cw0);
            cw0 = fmaf(siluf(acc0.z), w2.z, cw0);
            cw0 = fmaf(siluf(acc0.w), w2.w, cw0);
            cw1 = fmaf(siluf(acc1.x), w2.x, cw1);
            cw1 = fmaf(siluf(acc1.y), w2.y, cw1);
            cw1 = fmaf(siluf(acc1.z), w2.z, cw1);
            cw1 = fmaf(siluf(acc1.w), w2.w, cw1);
        }

        if (jv){
            #pragma unroll
            for (int t = 0; t < MD; t++) macc0[t] += me0[t];
            cr0x = fmaf(cw0, r0x, cr0x);
            cr0y = fmaf(cw0, r0y, cr0y);
            cr0z = fmaf(cw0, r0z, cr0z);
            if (iv1){
                #pragma unroll
                for (int t = 0; t < MD; t++) macc1[t] += me1[t];
                cr1x = fmaf(cw1, r1x, cr1x);
                cr1y = fmaf(cw1, r1y, cr1y);
                cr1z = fmaf(cw1, r1z, cr1z);
            }
        }
    }

    if (iv0){
        #pragma unroll
        for (int t = 0; t < MD; t++){
            float v = macc0[t];
            for (int off = 16; off; off >>= 1) v += __shfl_xor_sync(0xffffffffu, v, off);
            if (lane == 0) atomicAdd(&g_mi[ia*MD + t], v);
        }
        float v;
        v = cr0x; for (int off = 16; off; off >>= 1) v += __shfl_xor_sync(0xffffffffu, v, off);
        if (lane == 0) atomicAdd(&cnext[ia*3 + 0], v);
        v = cr0y; for (int off = 16; off; off >>= 1) v += __shfl_xor_sync(0xffffffffu, v, off);
        if (lane == 0) atomicAdd(&cnext[ia*3 + 1], v);
        v = cr0z; for (int off = 16; off; off >>= 1) v += __shfl_xor_sync(0xffffffffu, v, off);
        if (lane == 0) atomicAdd(&cnext[ia*3 + 2], v);
    }
    if (iv1){
        #pragma unroll
        for (int t = 0; t < MD; t++){
            float v = macc1[t];
            for (int off = 16; off; off >>= 1) v += __shfl_xor_sync(0xffffffffu, v, off);
            if (lane == 0) atomicAdd(&g_mi[ib*MD + t], v);
        }
        float v;
        v = cr1x; for (int off = 16; off; off >>= 1) v += __shfl_xor_sync(0xffffffffu, v, off);
        if (lane == 0) atomicAdd(&cnext[ib*3 + 0], v);
        v = cr1y; for (int off = 16; off; off >>= 1) v += __shfl_xor_sync(0xffffffffu, v, off);
        if (lane == 0) atomicAdd(&cnext[ib*3 + 1], v);
        v = cr1z; for (int off = 16; off; off >>= 1) v += __shfl_xor_sync(0xffffffffu, v, off);
        if (lane == 0) atomicAdd(&cnext[ib*3 + 2], v);
    }
}

// node MLP + double residual + relu: hc = relu(2*hc + MLP([hc, m_i]))
__global__ void k_node(int n, const float* __restrict__ Wn1L, const float* __restrict__ bn1L,
                       const float* __restrict__ Wn2L, const float* __restrict__ bn2L){
    __shared__ float in[81];
    __shared__ float z[128];
    int i = blockIdx.x, tid = threadIdx.x;
    if (tid < DIMF) in[tid] = g_hc[i*DIMF + tid];
    else if (tid < 81) in[tid] = g_mi[i*MD + (tid - DIMF)];
    __syncthreads();
    float acc = bn1L[tid];
    #pragma unroll 1
    for (int k = 0; k < 81; k++) acc = fmaf(in[k], Wn1L[k*128 + tid], acc);
    z[tid] = siluf(acc);
    __syncthreads();
    if (tid < DIMF){
        float a2 = bn2L[tid];
        #pragma unroll 1
        for (int k = 0; k < 128; k++) a2 = fmaf(z[k], Wn2L[k*DIMF + tid], a2);
        float v = 2.0f*in[tid] + a2;
        g_hc[i*DIMF + tid] = fmaxf(v, 0.0f);
    }
}

__global__ void k_scatter(float* out){
    int i = blockIdx.x, t = threadIdx.x;
    int a = g_idx[i];
    float v = g_hc[i*DIMF + t];
    float* o = &out[a*DIMF + t];
    *o = fmaxf(*o, v);
}

// ---------------- host ----------------
extern "C" void kernel_launch(void* const* d_in, const int* in_sizes, int n_in,
                              void* d_out, int out_size){
    const float* feat = (const float*)d_in[0];
    const float* coor = (const float*)d_in[1];
    const float* edge = (const float*)d_in[2];
    const float* We1  = (const float*)d_in[3];
    const float* be1  = (const float*)d_in[4];
    const float* We2  = (const float*)d_in[5];
    const float* be2  = (const float*)d_in[6];
    const float* Wc1  = (const float*)d_in[7];
    const float* bc1  = (const float*)d_in[8];
    const float* Wc2  = (const float*)d_in[9];
    const float* bc2  = (const float*)d_in[10];
    const float* Wn1  = (const float*)d_in[11];
    const float* bn1  = (const float*)d_in[12];
    const float* Wn2  = (const float*)d_in[13];
    const float* bn2  = (const float*)d_in[14];
    const float* wp   = (const float*)d_in[15];
    const float* bp   = (const float*)d_in[16];
    float* out = (float*)d_out;

    static const int KC[3] = {460, 358, 307};
    const int EDGE_SMEM = 17792 * 4;          // 71168 B
    cudaFuncSetAttribute(k_edge, cudaFuncAttributeMaxDynamicSharedMemorySize, EDGE_SMEM);

    k_zero_out<<<128, 256>>>(out);
    k_ugbits<<<512, 512>>>(edge);
    k_ug2<<<512, 32>>>();

    for (int p = 0; p < 3; p++){
        int n = KC[p];
        k_scores<<<128, 128>>>(feat, wp, bp, p);
        k_select2<<<1, 512>>>(n);
        k_gather<<<n, 64>>>(feat, coor);
        k_gsub<<<n, 32>>>(n);
        for (int l = 0; l < 3; l++){
            k_AB<<<n, 256>>>(n, We1 + l*130*H1, be1 + l*H1);
            int gi = (n*(MD+3) + 255) / 256;
            k_init<<<gi, 256>>>(n, l & 1);
            dim3 ge((n + RPB - 1) / RPB, NSPL);
            k_edge<<<ge, 128, EDGE_SMEM>>>(n, l & 1,
                We1 + l*130*H1, We2 + l*H1*MD, be2 + l*MD,
                Wc1 + l*MD*CHID, bc1 + l*CHID, Wc2 + l*CHID, bc2 + l);
            k_node<<<n, 128>>>(n, Wn1 + l*81*128, bn1 + l*128, Wn2 + l*128*DIMF, bn2 + l*DIMF);
        }
        k_scatter<<<n, 64>>>(out);
    }
}